// round 6
// baseline (speedup 1.0000x reference)
#include <cuda_runtime.h>
#include <cstdint>

#define N_PTS  65536
#define M_G    1024
#define KSEL   10
#define TPB    256
#define SPLIT  4
#define SLICE  256          // M_G / SPLIT
#define FRZ    64           // exact-sift prefix per lane
#define CAPL   16           // per-lane B-candidate cap
#define EQCAP  8
#define NBLK   512          // persistent CTAs (single wave @ 4/SM on 148 SMs)
#define NTILE  2            // point-tiles per CTA  (NBLK*NTILE*TPB/SPLIT == N_PTS)
#define NEGINF (-3.402823466e38f)

// Offset form: q(x) = d^T P' d,  d = x - mu,  P' = -0.5*log2(e) * Sigma^-1.
// weight = exp2(q). Interleaved: gaussian m = s*256+i lives at pos = 4*i + s.
__device__ float4 g_p1[M_G];   // mu0, mu1, p00, p01
__device__ float2 g_p2[M_G];   // p11, (pad)

__global__ void prep_kernel(const float* __restrict__ mus,
                            const float* __restrict__ covs) {
    int m = blockIdx.x * blockDim.x + threadIdx.x;
    if (m >= M_G) return;
    float mu0 = mus[2 * m], mu1 = mus[2 * m + 1];
    float a = covs[4 * m + 0];
    float b = covs[4 * m + 1];   // symmetric
    float c = covs[4 * m + 3];
    float det = a * c - b * b;
    const float L2E = 1.4426950408889634f;
    float sc = -0.5f * L2E / det;
    float p00 = sc * c;
    float p01 = -sc * b;
    float p11 = sc * a;
    int s = m >> 8, i = m & (SLICE - 1);
    int pos = i * SPLIT + s;
    g_p1[pos] = make_float4(mu0, mu1, p00, p01);
    g_p2[pos] = make_float2(p11, 0.f);
}

__device__ __forceinline__ float ex2_approx(float x) {
    float r;
    asm("ex2.approx.ftz.f32 %0, %1;" : "=f"(r) : "f"(x));
    return r;
}

// Depth-2 branchless sorted insert into descending top[0..9] (exact fp32).
__device__ __forceinline__ void siftf(float top[KSEL], float q) {
    float mn[KSEL - 1];
    #pragma unroll
    for (int j = 1; j < KSEL; ++j) mn[j - 1] = fminf(q, top[j - 1]);
    #pragma unroll
    for (int j = 1; j < KSEL; ++j) top[j] = fmaxf(mn[j - 1], top[j]);
    top[0] = fmaxf(top[0], q);
}

__global__ void __launch_bounds__(TPB, 4) render_kernel(
    const float2* __restrict__ x,
    const float*  __restrict__ cols,
    float*        __restrict__ out)
{
    __shared__ float4        sp1[M_G];
    __shared__ float2        sp2[M_G];
    __shared__ float         candq[TPB * CAPL];
    __shared__ unsigned char candi[TPB * CAPL];
    __shared__ unsigned char seq  [TPB * EQCAP];

    int tid = threadIdx.x;
    #pragma unroll 4
    for (int i = tid; i < M_G; i += TPB) { sp1[i] = g_p1[i]; sp2[i] = g_p2[i]; }
    __syncthreads();

    int s = tid & 3;            // slice (lanes 4k..4k+3 share a point)

    #pragma unroll 1
    for (int tile = 0; tile < NTILE; ++tile) {
        int tileIdx = blockIdx.x + tile * NBLK;
        int gt_ = tileIdx * TPB + tid;
        int p   = gt_ >> 2;         // point index
        float2 xv = __ldg(&x[p]);
        float x0 = xv.x, x1 = xv.y;

        // identical expression everywhere -> bitwise-reproducible q
        auto evalq = [&](int i) -> float {
            float4 c1 = sp1[i * 4 + s];       // mu0, mu1, p00, p01
            float2 c2 = sp2[i * 4 + s];       // p11
            float d0 = x0 - c1.x;
            float d1 = x1 - c1.y;
            float t0 = fmaf(c1.w, d1, c1.z * d0);   // p00*d0 + p01*d1
            float t1 = fmaf(c2.x, d1, c1.w * d0);   // p01*d0 + p11*d1
            return fmaf(d1, t1, d0 * t0);           // d^T P' d  (log2 weight)
        };

        float top[KSEL];
        #pragma unroll
        for (int j = 0; j < KSEL; ++j) top[j] = NEGINF;

        // ---- Phase A: exact sift over first FRZ of own slice ----
        #pragma unroll 2
        for (int i = 0; i < FRZ; ++i) siftf(top, evalq(i));

        // merge the 4 lane lists -> exact top-10 of the 256 sampled
        #pragma unroll
        for (int st = 1; st <= 2; st <<= 1) {
            float cur[KSEL];
            #pragma unroll
            for (int j = 0; j < KSEL; ++j) cur[j] = top[j];
            #pragma unroll
            for (int j = 0; j < KSEL; ++j)
                siftf(top, __shfl_xor_sync(0xFFFFFFFFu, cur[j], st));
        }
        float tau = top[KSEL - 1];   // exact lower bound on the final 10th

        // ---- Phase B: guard + log (q, i) survivors ----
        int cnt = 0;
        #pragma unroll 4
        for (int i = FRZ; i < SLICE; ++i) {
            float q = evalq(i);
            if (q >= tau) {
                if (cnt < CAPL) {
                    candq[tid * CAPL + cnt] = q;
                    candi[tid * CAPL + cnt] = (unsigned char)i;
                }
                cnt++;
            }
        }
        bool ovf = (cnt > CAPL);

        // ---- exact 10th: lane B-list -> merge -> fold into A-list ----
        float L[KSEL];
        #pragma unroll
        for (int j = 0; j < KSEL; ++j) L[j] = NEGINF;
        if (!ovf) {
            for (int j = 0; j < cnt; ++j) siftf(L, candq[tid * CAPL + j]);
        } else {
            for (int i = FRZ; i < SLICE; ++i) siftf(L, evalq(i));  // exact fallback
        }
        #pragma unroll
        for (int st = 1; st <= 2; st <<= 1) {
            float cur[KSEL];
            #pragma unroll
            for (int j = 0; j < KSEL; ++j) cur[j] = L[j];
            #pragma unroll
            for (int j = 0; j < KSEL; ++j)
                siftf(L, __shfl_xor_sync(0xFFFFFFFFu, cur[j], st));
        }
        #pragma unroll
        for (int j = 0; j < KSEL; ++j) siftf(top, L[j]);
        float t = top[KSEL - 1];     // exact 10th-largest q of all 1024

        // ---- accumulate winners; q==t ties logged for lowest-m quota fill ----
        float r0 = 0.f, r1 = 0.f, r2 = 0.f, den = 0.f;
        int gtc = 0, eqc = 0;

        auto acc = [&](int i, float q) {
            int m = s * SLICE + i;
            float v = ex2_approx(q);
            r0 = fmaf(v, __ldg(&cols[3 * m + 0]), r0);
            r1 = fmaf(v, __ldg(&cols[3 * m + 1]), r1);
            r2 = fmaf(v, __ldg(&cols[3 * m + 2]), r2);
            den += v;
        };

        #pragma unroll 2
        for (int i = 0; i < FRZ; ++i) {           // A-range rescan
            float q = evalq(i);
            if (q > t)       { acc(i, q); gtc++; }
            else if (q == t) { if (eqc < EQCAP) seq[tid * EQCAP + eqc] = (unsigned char)i; eqc++; }
        }
        if (!ovf) {                               // B winners from the log
            for (int j = 0; j < cnt; ++j) {
                float q = candq[tid * CAPL + j];
                int   i = candi[tid * CAPL + j];
                if (q > t)       { acc(i, q); gtc++; }
                else if (q == t) { if (eqc < EQCAP) seq[tid * EQCAP + eqc] = (unsigned char)i; eqc++; }
            }
        } else {                                  // exact fallback rescan
            for (int i = FRZ; i < SLICE; ++i) {
                float q = evalq(i);
                if (q > t)       { acc(i, q); gtc++; }
                else if (q == t) { if (eqc < EQCAP) seq[tid * EQCAP + eqc] = (unsigned char)i; eqc++; }
            }
        }
        if (eqc > EQCAP) eqc = EQCAP;

        // group totals + lane-ordered (== ascending m) tie quota
        int gt_tot = gtc;
        gt_tot += __shfl_xor_sync(0xFFFFFFFFu, gt_tot, 1);
        gt_tot += __shfl_xor_sync(0xFFFFFFFFu, gt_tot, 2);
        int lane = tid & 31, base = lane & ~3;
        int e0 = __shfl_sync(0xFFFFFFFFu, eqc, base + 0);
        int e1 = __shfl_sync(0xFFFFFFFFu, eqc, base + 1);
        int e2 = __shfl_sync(0xFFFFFFFFu, eqc, base + 2);
        int prefix = (s > 0 ? e0 : 0) + (s > 1 ? e1 : 0) + (s > 2 ? e2 : 0);
        int keep_eq = KSEL - gt_tot;              // >= 1 by definition of t
        int quota = min(eqc, max(0, keep_eq - prefix));
        for (int j = 0; j < quota; ++j) acc((int)seq[tid * EQCAP + j], t);

        // group reduction
        #pragma unroll
        for (int st = 1; st <= 2; st <<= 1) {
            r0  += __shfl_xor_sync(0xFFFFFFFFu, r0,  st);
            r1  += __shfl_xor_sync(0xFFFFFFFFu, r1,  st);
            r2  += __shfl_xor_sync(0xFFFFFFFFu, r2,  st);
            den += __shfl_xor_sync(0xFFFFFFFFu, den, st);
        }

        if (s == 0) {
            float inv = 1.0f / (den + 1e-6f);
            out[3 * p + 0] = r0 * inv;
            out[3 * p + 1] = r1 * inv;
            out[3 * p + 2] = r2 * inv;
        }
    }
}

extern "C" void kernel_launch(void* const* d_in, const int* in_sizes, int n_in,
                              void* d_out, int out_size) {
    const float* xx   = (const float*)d_in[0];   // [N, 2]
    const float* mus  = (const float*)d_in[1];   // [1, M, 2]
    const float* covs = (const float*)d_in[2];   // [1, M, 2, 2]
    const float* cols = (const float*)d_in[3];   // [1, M, 3]
    float* out = (float*)d_out;                  // [N, 3]

    prep_kernel<<<(M_G + 127) / 128, 128>>>(mus, covs);
    render_kernel<<<NBLK, TPB>>>((const float2*)xx, cols, out);
}

// round 7
// speedup vs baseline: 1.2778x; 1.2778x over previous
#include <cuda_runtime.h>
#include <cstdint>

#define N_PTS  65536
#define M_G    1024
#define KSEL   10
#define TPB    256
#define SPLIT  4
#define SLICE  256          // M_G / SPLIT
#define FRZ    64           // exact-sift prefix per lane
#define CAPL   16           // per-lane B-candidate cap
#define EQCAP  4
#define POSINF (3.402823466e38f)

// Cholesky-affine form: h(x) = u0^2 + u1^2 = d^T M d,  M = 0.5*log2(e)*Sigma^-1 = L L^T,
//   u0 = l00*x0 + l10*x1 + k0,  u1 = l11*x1 + k1   (k folds in -L^T mu).
// weight = exp2(-h); top-k largest weight == top-k SMALLEST h.
// Interleaved: gaussian m = s*256+i lives at pos = 4*i + s.
__device__ float4 g_c4[M_G];   // l00, l10, k0, l11
__device__ float  g_k1[M_G];   // k1

__global__ void prep_kernel(const float* __restrict__ mus,
                            const float* __restrict__ covs) {
    int m = blockIdx.x * blockDim.x + threadIdx.x;
    if (m >= M_G) return;
    float mu0 = mus[2 * m], mu1 = mus[2 * m + 1];
    float a = covs[4 * m + 0];
    float b = covs[4 * m + 1];   // symmetric
    float c = covs[4 * m + 3];
    float det = a * c - b * b;
    const float L2E = 1.4426950408889634f;
    float sc = 0.5f * L2E / det;          // positive (Sigma SPD)
    float m00 = sc * c;
    float m01 = -sc * b;
    float m11 = sc * a;
    float l00 = sqrtf(m00);
    float l10 = m01 / l00;
    float l11 = sqrtf(m11 - l10 * l10);
    float k0  = -(l00 * mu0 + l10 * mu1);
    float k1  = -l11 * mu1;
    int s = m >> 8, i = m & (SLICE - 1);
    int pos = i * SPLIT + s;
    g_c4[pos] = make_float4(l00, l10, k0, l11);
    g_k1[pos] = k1;
}

__device__ __forceinline__ float ex2_approx(float x) {
    float r;
    asm("ex2.approx.ftz.f32 %0, %1;" : "=f"(r) : "f"(x));
    return r;
}

// Depth-2 branchless sorted insert into ASCENDING top[0..9] (keep 10 smallest).
__device__ __forceinline__ void siftf(float top[KSEL], float h) {
    float mx[KSEL - 1];
    #pragma unroll
    for (int j = 1; j < KSEL; ++j) mx[j - 1] = fmaxf(h, top[j - 1]);
    #pragma unroll
    for (int j = 1; j < KSEL; ++j) top[j] = fminf(mx[j - 1], top[j]);
    top[0] = fminf(top[0], h);
}

__global__ void __launch_bounds__(TPB, 5) render_kernel(
    const float2* __restrict__ x,
    const float*  __restrict__ cols,
    float*        __restrict__ out)
{
    __shared__ float4        sc4[M_G];               // 16 KB
    __shared__ float         sk1[M_G];               //  4 KB
    __shared__ float         candq[TPB * CAPL];      // 16 KB
    __shared__ unsigned char candi[TPB * CAPL];      //  4 KB
    __shared__ unsigned char seq  [TPB * EQCAP];     //  1 KB

    int tid = threadIdx.x;
    #pragma unroll 4
    for (int i = tid; i < M_G; i += TPB) { sc4[i] = g_c4[i]; sk1[i] = g_k1[i]; }
    __syncthreads();

    int gt_ = blockIdx.x * TPB + tid;
    int p   = gt_ >> 2;         // point
    int s   = gt_ & 3;          // slice (lanes 4k..4k+3 share a point)
    float2 xv = __ldg(&x[p]);
    float x0 = xv.x, x1 = xv.y;

    // identical expression everywhere -> bitwise-reproducible h
    auto evalh = [&](int i) -> float {
        float4 c1 = sc4[i * 4 + s];       // l00, l10, k0, l11
        float k1 = sk1[i * 4 + s];
        float u0 = fmaf(c1.x, x0, fmaf(c1.y, x1, c1.z));
        float u1 = fmaf(c1.w, x1, k1);
        return fmaf(u0, u0, u1 * u1);     // = d^T M d  (>=0)
    };

    float top[KSEL];
    #pragma unroll
    for (int j = 0; j < KSEL; ++j) top[j] = POSINF;

    // ---- Phase A: exact min-sift over first FRZ of own slice ----
    #pragma unroll 2
    for (int i = 0; i < FRZ; ++i) siftf(top, evalh(i));

    // merge the 4 lane lists -> exact 10-smallest of the 256 sampled
    #pragma unroll
    for (int st = 1; st <= 2; st <<= 1) {
        float cur[KSEL];
        #pragma unroll
        for (int j = 0; j < KSEL; ++j) cur[j] = top[j];
        #pragma unroll
        for (int j = 0; j < KSEL; ++j)
            siftf(top, __shfl_xor_sync(0xFFFFFFFFu, cur[j], st));
    }
    float tau = top[KSEL - 1];   // exact 10th-smallest of sample >= true 10th-smallest

    // ---- Phase B: guard + log (h, i) survivors ----
    int cnt = 0;
    #pragma unroll 4
    for (int i = FRZ; i < SLICE; ++i) {
        float h = evalh(i);
        if (h <= tau) {
            if (cnt < CAPL) {
                candq[tid * CAPL + cnt] = h;
                candi[tid * CAPL + cnt] = (unsigned char)i;
            }
            cnt++;
        }
    }
    bool ovf = (cnt > CAPL);

    // ---- exact 10th-smallest overall: lane B-list -> merge -> fold ----
    float L[KSEL];
    #pragma unroll
    for (int j = 0; j < KSEL; ++j) L[j] = POSINF;
    if (!ovf) {
        for (int j = 0; j < cnt; ++j) siftf(L, candq[tid * CAPL + j]);
    } else {
        for (int i = FRZ; i < SLICE; ++i) siftf(L, evalh(i));  // exact fallback
    }
    #pragma unroll
    for (int st = 1; st <= 2; st <<= 1) {
        float cur[KSEL];
        #pragma unroll
        for (int j = 0; j < KSEL; ++j) cur[j] = L[j];
        #pragma unroll
        for (int j = 0; j < KSEL; ++j)
            siftf(L, __shfl_xor_sync(0xFFFFFFFFu, cur[j], st));
    }
    #pragma unroll
    for (int j = 0; j < KSEL; ++j) siftf(top, L[j]);
    float t = top[KSEL - 1];     // exact 10th-smallest h of all 1024

    // ---- accumulate winners (h < t); h == t ties logged for quota fill ----
    float r0 = 0.f, r1 = 0.f, r2 = 0.f, den = 0.f;
    int ltc = 0, eqc = 0;

    auto acc = [&](int i, float h) {
        int m = s * SLICE + i;
        float v = ex2_approx(-h);
        r0 = fmaf(v, __ldg(&cols[3 * m + 0]), r0);
        r1 = fmaf(v, __ldg(&cols[3 * m + 1]), r1);
        r2 = fmaf(v, __ldg(&cols[3 * m + 2]), r2);
        den += v;
    };

    #pragma unroll 2
    for (int i = 0; i < FRZ; ++i) {           // A-range rescan
        float h = evalh(i);
        if (h < t)       { acc(i, h); ltc++; }
        else if (h == t) { if (eqc < EQCAP) seq[tid * EQCAP + eqc] = (unsigned char)i; eqc++; }
    }
    if (!ovf) {                               // B winners from the log
        for (int j = 0; j < cnt; ++j) {
            float h = candq[tid * CAPL + j];
            int   i = candi[tid * CAPL + j];
            if (h < t)       { acc(i, h); ltc++; }
            else if (h == t) { if (eqc < EQCAP) seq[tid * EQCAP + eqc] = (unsigned char)i; eqc++; }
        }
    } else {                                  // exact fallback rescan
        for (int i = FRZ; i < SLICE; ++i) {
            float h = evalh(i);
            if (h < t)       { acc(i, h); ltc++; }
            else if (h == t) { if (eqc < EQCAP) seq[tid * EQCAP + eqc] = (unsigned char)i; eqc++; }
        }
    }
    if (eqc > EQCAP) eqc = EQCAP;

    // group totals + lane-ordered (== ascending m) tie quota
    int lt_tot = ltc;
    lt_tot += __shfl_xor_sync(0xFFFFFFFFu, lt_tot, 1);
    lt_tot += __shfl_xor_sync(0xFFFFFFFFu, lt_tot, 2);
    int lane = tid & 31, base = lane & ~3;
    int e0 = __shfl_sync(0xFFFFFFFFu, eqc, base + 0);
    int e1 = __shfl_sync(0xFFFFFFFFu, eqc, base + 1);
    int e2 = __shfl_sync(0xFFFFFFFFu, eqc, base + 2);
    int prefix = (s > 0 ? e0 : 0) + (s > 1 ? e1 : 0) + (s > 2 ? e2 : 0);
    int keep_eq = KSEL - lt_tot;              // >= 1 by definition of t
    int quota = min(eqc, max(0, keep_eq - prefix));
    for (int j = 0; j < quota; ++j) acc((int)seq[tid * EQCAP + j], t);

    // group reduction
    #pragma unroll
    for (int st = 1; st <= 2; st <<= 1) {
        r0  += __shfl_xor_sync(0xFFFFFFFFu, r0,  st);
        r1  += __shfl_xor_sync(0xFFFFFFFFu, r1,  st);
        r2  += __shfl_xor_sync(0xFFFFFFFFu, r2,  st);
        den += __shfl_xor_sync(0xFFFFFFFFu, den, st);
    }

    if (s == 0) {
        float inv = 1.0f / (den + 1e-6f);
        out[3 * p + 0] = r0 * inv;
        out[3 * p + 1] = r1 * inv;
        out[3 * p + 2] = r2 * inv;
    }
}

extern "C" void kernel_launch(void* const* d_in, const int* in_sizes, int n_in,
                              void* d_out, int out_size) {
    const float* xx   = (const float*)d_in[0];   // [N, 2]
    const float* mus  = (const float*)d_in[1];   // [1, M, 2]
    const float* covs = (const float*)d_in[2];   // [1, M, 2, 2]
    const float* cols = (const float*)d_in[3];   // [1, M, 3]
    float* out = (float*)d_out;                  // [N, 3]

    prep_kernel<<<(M_G + 127) / 128, 128>>>(mus, covs);
    render_kernel<<<(N_PTS * SPLIT) / TPB, TPB>>>((const float2*)xx, cols, out);
}

// round 8
// speedup vs baseline: 1.3435x; 1.0514x over previous
#include <cuda_runtime.h>
#include <cstdint>

#define N_PTS  65536
#define M_G    1024
#define KSEL   10
#define TPB    256
#define SPLIT  4
#define SLICE  256          // M_G / SPLIT
#define NPAIR  128          // SLICE / 2
#define FRZP   32           // exact-sift prefix per lane, in PAIRS (=64 gaussians)
#define CAPL   16           // per-lane B-candidate cap
#define EQCAP  4
#define POSINF (3.402823466e38f)

typedef unsigned long long ull;

// Cholesky-affine form: h(x) = u0^2 + u1^2,  u0 = l00*x0 + l10*x1 + k0,
// u1 = l11*x1 + k1;  weight = exp2(-h); top-k largest weight == k SMALLEST h.
// PAIR-PACKED storage: pair slot = j*4 + s holds gaussians m=(s*256+2j, s*256+2j+1):
//   g_ab4[slot] = (l00_a, l00_b, l10_a, l10_b)
//   g_cd4[slot] = (k0_a,  k0_b,  l11_a, l11_b)
//   g_ef2[slot] = (k1_a,  k1_b)
// so an LDS.128 puts each f32x2 operand directly into a register pair.
__device__ float4 g_ab4[M_G / 2];
__device__ float4 g_cd4[M_G / 2];
__device__ float2 g_ef2[M_G / 2];

__global__ void prep_kernel(const float* __restrict__ mus,
                            const float* __restrict__ covs) {
    int m = blockIdx.x * blockDim.x + threadIdx.x;
    if (m >= M_G) return;
    float mu0 = mus[2 * m], mu1 = mus[2 * m + 1];
    float a = covs[4 * m + 0];
    float b = covs[4 * m + 1];   // symmetric
    float c = covs[4 * m + 3];
    float det = a * c - b * b;
    const float L2E = 1.4426950408889634f;
    float sc = 0.5f * L2E / det;          // positive (Sigma SPD)
    float m00 = sc * c;
    float m01 = -sc * b;
    float m11 = sc * a;
    float l00 = sqrtf(m00);
    float l10 = m01 / l00;
    float l11 = sqrtf(m11 - l10 * l10);
    float k0  = -(l00 * mu0 + l10 * mu1);
    float k1  = -l11 * mu1;
    int s = m >> 8, i = m & (SLICE - 1);
    int j = i >> 1, half = i & 1;
    int slot = j * 4 + s;
    float* ab = (float*)g_ab4;
    float* cd = (float*)g_cd4;
    float* ef = (float*)g_ef2;
    ab[slot * 4 + 0 + half] = l00;
    ab[slot * 4 + 2 + half] = l10;
    cd[slot * 4 + 0 + half] = k0;
    cd[slot * 4 + 2 + half] = l11;
    ef[slot * 2 + half]     = k1;
}

__device__ __forceinline__ float ex2_approx(float x) {
    float r;
    asm("ex2.approx.ftz.f32 %0, %1;" : "=f"(r) : "f"(x));
    return r;
}
__device__ __forceinline__ ull fma2(ull a, ull b, ull c) {
    ull d;
    asm("fma.rn.f32x2 %0, %1, %2, %3;" : "=l"(d) : "l"(a), "l"(b), "l"(c));
    return d;
}
__device__ __forceinline__ ull mul2(ull a, ull b) {
    ull d;
    asm("mul.rn.f32x2 %0, %1, %2;" : "=l"(d) : "l"(a), "l"(b));
    return d;
}
__device__ __forceinline__ ull pack2(float lo, float hi) {
    ull d;
    asm("mov.b64 %0, {%1, %2};" : "=l"(d) : "f"(lo), "f"(hi));
    return d;
}
__device__ __forceinline__ void unpack2(float& lo, float& hi, ull v) {
    asm("mov.b64 {%0, %1}, %2;" : "=f"(lo), "=f"(hi) : "l"(v));
}

// Depth-2 branchless sorted insert into ASCENDING top[0..9] (keep 10 smallest).
__device__ __forceinline__ void siftf(float top[KSEL], float h) {
    float mx[KSEL - 1];
    #pragma unroll
    for (int j = 1; j < KSEL; ++j) mx[j - 1] = fmaxf(h, top[j - 1]);
    #pragma unroll
    for (int j = 1; j < KSEL; ++j) top[j] = fminf(mx[j - 1], top[j]);
    top[0] = fminf(top[0], h);
}

__global__ void __launch_bounds__(TPB, 5) render_kernel(
    const float2* __restrict__ x,
    const float*  __restrict__ cols,
    float*        __restrict__ out)
{
    __shared__ float4        s_ab[M_G / 2];           // 8 KB
    __shared__ float4        s_cd[M_G / 2];           // 8 KB
    __shared__ float2        s_ef[M_G / 2];           // 4 KB
    __shared__ float         candq[TPB * CAPL];       // 16 KB
    __shared__ unsigned char candi[TPB * CAPL];       //  4 KB
    __shared__ unsigned char seq  [TPB * EQCAP];      //  1 KB

    int tid = threadIdx.x;
    #pragma unroll 2
    for (int i = tid; i < M_G / 2; i += TPB) {
        s_ab[i] = g_ab4[i];
        s_cd[i] = g_cd4[i];
        s_ef[i] = g_ef2[i];
    }
    __syncthreads();

    int gt_ = blockIdx.x * TPB + tid;
    int p   = gt_ >> 2;         // point
    int s   = gt_ & 3;          // slice (lanes 4k..4k+3 share a point)
    float2 xv = __ldg(&x[p]);
    ull X0 = pack2(xv.x, xv.x);
    ull X1 = pack2(xv.y, xv.y);

    // Evaluate gaussian pair jp of own slice; identical instruction sequence on
    // every call -> bitwise-reproducible (h_a, h_b).
    auto evalpair = [&](int jp) -> ull {
        const ulonglong2 ab = *reinterpret_cast<const ulonglong2*>(&s_ab[jp * 4 + s]);
        const ulonglong2 cd = *reinterpret_cast<const ulonglong2*>(&s_cd[jp * 4 + s]);
        const ull        ef = *reinterpret_cast<const ull*>(&s_ef[jp * 4 + s]);
        ull u0 = fma2(ab.x, X0, fma2(ab.y, X1, cd.x));   // l00*x0 + l10*x1 + k0
        ull u1 = fma2(cd.y, X1, ef);                     // l11*x1 + k1
        return fma2(u0, u0, mul2(u1, u1));               // h pair (>= 0)
    };

    float top[KSEL];
    #pragma unroll
    for (int j = 0; j < KSEL; ++j) top[j] = POSINF;

    // ---- Phase A: exact min-sift over first FRZP pairs of own slice ----
    #pragma unroll 2
    for (int jp = 0; jp < FRZP; ++jp) {
        float ha, hb;
        unpack2(ha, hb, evalpair(jp));
        siftf(top, ha);
        siftf(top, hb);
    }

    // merge the 4 lane lists -> exact 10-smallest of the 256 sampled
    #pragma unroll
    for (int st = 1; st <= 2; st <<= 1) {
        float cur[KSEL];
        #pragma unroll
        for (int j = 0; j < KSEL; ++j) cur[j] = top[j];
        #pragma unroll
        for (int j = 0; j < KSEL; ++j)
            siftf(top, __shfl_xor_sync(0xFFFFFFFFu, cur[j], st));
    }
    float tau = top[KSEL - 1];   // exact 10th-smallest of sample >= true 10th

    // ---- Phase B: guard + log (h, i) survivors ----
    int cnt = 0;
    #pragma unroll 2
    for (int jp = FRZP; jp < NPAIR; ++jp) {
        float ha, hb;
        unpack2(ha, hb, evalpair(jp));
        if (ha <= tau) {
            if (cnt < CAPL) {
                candq[tid * CAPL + cnt] = ha;
                candi[tid * CAPL + cnt] = (unsigned char)(2 * jp);
            }
            cnt++;
        }
        if (hb <= tau) {
            if (cnt < CAPL) {
                candq[tid * CAPL + cnt] = hb;
                candi[tid * CAPL + cnt] = (unsigned char)(2 * jp + 1);
            }
            cnt++;
        }
    }
    bool ovf = (cnt > CAPL);

    // ---- exact 10th-smallest overall: lane B-list -> merge -> fold ----
    float L[KSEL];
    #pragma unroll
    for (int j = 0; j < KSEL; ++j) L[j] = POSINF;
    if (!ovf) {
        for (int j = 0; j < cnt; ++j) siftf(L, candq[tid * CAPL + j]);
    } else {
        for (int jp = FRZP; jp < NPAIR; ++jp) {     // exact fallback
            float ha, hb;
            unpack2(ha, hb, evalpair(jp));
            siftf(L, ha);
            siftf(L, hb);
        }
    }
    #pragma unroll
    for (int st = 1; st <= 2; st <<= 1) {
        float cur[KSEL];
        #pragma unroll
        for (int j = 0; j < KSEL; ++j) cur[j] = L[j];
        #pragma unroll
        for (int j = 0; j < KSEL; ++j)
            siftf(L, __shfl_xor_sync(0xFFFFFFFFu, cur[j], st));
    }
    #pragma unroll
    for (int j = 0; j < KSEL; ++j) siftf(top, L[j]);
    float t = top[KSEL - 1];     // exact 10th-smallest h of all 1024

    // ---- accumulate winners (h < t); h == t ties logged for quota fill ----
    float r0 = 0.f, r1 = 0.f, r2 = 0.f, den = 0.f;
    int ltc = 0, eqc = 0;

    auto acc = [&](int i, float h) {
        int m = s * SLICE + i;
        float v = ex2_approx(-h);
        r0 = fmaf(v, __ldg(&cols[3 * m + 0]), r0);
        r1 = fmaf(v, __ldg(&cols[3 * m + 1]), r1);
        r2 = fmaf(v, __ldg(&cols[3 * m + 2]), r2);
        den += v;
    };
    auto consider = [&](int i, float h) {
        if (h < t)       { acc(i, h); ltc++; }
        else if (h == t) { if (eqc < EQCAP) seq[tid * EQCAP + eqc] = (unsigned char)i; eqc++; }
    };

    #pragma unroll 2
    for (int jp = 0; jp < FRZP; ++jp) {       // A-range rescan
        float ha, hb;
        unpack2(ha, hb, evalpair(jp));
        consider(2 * jp, ha);
        consider(2 * jp + 1, hb);
    }
    if (!ovf) {                               // B winners from the log
        for (int j = 0; j < cnt; ++j)
            consider((int)candi[tid * CAPL + j], candq[tid * CAPL + j]);
    } else {                                  // exact fallback rescan
        for (int jp = FRZP; jp < NPAIR; ++jp) {
            float ha, hb;
            unpack2(ha, hb, evalpair(jp));
            consider(2 * jp, ha);
            consider(2 * jp + 1, hb);
        }
    }
    if (eqc > EQCAP) eqc = EQCAP;

    // group totals + lane-ordered (== ascending m) tie quota
    int lt_tot = ltc;
    lt_tot += __shfl_xor_sync(0xFFFFFFFFu, lt_tot, 1);
    lt_tot += __shfl_xor_sync(0xFFFFFFFFu, lt_tot, 2);
    int lane = tid & 31, base = lane & ~3;
    int e0 = __shfl_sync(0xFFFFFFFFu, eqc, base + 0);
    int e1 = __shfl_sync(0xFFFFFFFFu, eqc, base + 1);
    int e2 = __shfl_sync(0xFFFFFFFFu, eqc, base + 2);
    int prefix = (s > 0 ? e0 : 0) + (s > 1 ? e1 : 0) + (s > 2 ? e2 : 0);
    int keep_eq = KSEL - lt_tot;              // >= 1 by definition of t
    int quota = min(eqc, max(0, keep_eq - prefix));
    for (int j = 0; j < quota; ++j) acc((int)seq[tid * EQCAP + j], t);

    // group reduction
    #pragma unroll
    for (int st = 1; st <= 2; st <<= 1) {
        r0  += __shfl_xor_sync(0xFFFFFFFFu, r0,  st);
        r1  += __shfl_xor_sync(0xFFFFFFFFu, r1,  st);
        r2  += __shfl_xor_sync(0xFFFFFFFFu, r2,  st);
        den += __shfl_xor_sync(0xFFFFFFFFu, den, st);
    }

    if (s == 0) {
        float inv = 1.0f / (den + 1e-6f);
        out[3 * p + 0] = r0 * inv;
        out[3 * p + 1] = r1 * inv;
        out[3 * p + 2] = r2 * inv;
    }
}

extern "C" void kernel_launch(void* const* d_in, const int* in_sizes, int n_in,
                              void* d_out, int out_size) {
    const float* xx   = (const float*)d_in[0];   // [N, 2]
    const float* mus  = (const float*)d_in[1];   // [1, M, 2]
    const float* covs = (const float*)d_in[2];   // [1, M, 2, 2]
    const float* cols = (const float*)d_in[3];   // [1, M, 3]
    float* out = (float*)d_out;                  // [N, 3]

    prep_kernel<<<(M_G + 127) / 128, 128>>>(mus, covs);
    render_kernel<<<(N_PTS * SPLIT) / TPB, TPB>>>((const float2*)xx, cols, out);
}

// round 9
// speedup vs baseline: 4.7143x; 3.5090x over previous
#include <cuda_runtime.h>
#include <cstdint>

#define N_PTS  65536
#define M_G    1024
#define KSEL   10
#define GRIDC  32
#define NCELL  (GRIDC * GRIDC)
#define CAP    192
#define TPB    256
#define POSINF (3.402823466e38f)

// Cholesky-affine form: h(x) = u0^2 + u1^2,  u0 = l00*x0 + l10*x1 + k0,
// u1 = l11*x1 + k1;  weight = exp2(-h); top-k largest weight == k SMALLEST h.
__device__ float4 g_c4[M_G];                 // l00, l10, k0, l11
__device__ float  g_k1[M_G];                 // k1
__device__ unsigned short g_list[NCELL * CAP];  // per-cell candidate ids (ascending m)
__device__ int    g_cnt[NCELL];              // true candidate count (may exceed CAP)

__global__ void prep_kernel(const float* __restrict__ mus,
                            const float* __restrict__ covs) {
    int m = blockIdx.x * blockDim.x + threadIdx.x;
    if (m >= M_G) return;
    float mu0 = mus[2 * m], mu1 = mus[2 * m + 1];
    float a = covs[4 * m + 0];
    float b = covs[4 * m + 1];   // symmetric
    float c = covs[4 * m + 3];
    float det = a * c - b * b;
    const float L2E = 1.4426950408889634f;
    float sc = 0.5f * L2E / det;          // positive (Sigma SPD)
    float m00 = sc * c;
    float m01 = -sc * b;
    float m11 = sc * a;
    float l00 = sqrtf(m00);
    float l10 = m01 / l00;
    float l11 = sqrtf(m11 - l10 * l10);
    float k0  = -(l00 * mu0 + l10 * mu1);
    float k1  = -l11 * mu1;
    g_c4[m] = make_float4(l00, l10, k0, l11);
    g_k1[m] = k1;
}

// Per-cell candidate construction.
// hmax exact (convex h -> max at a box corner); hmin by interval relaxation
// (rigorous lower bound). T = upper bound on sup_{x in C} h_10th(x) via the
// 10th-smallest hmax (bisection). S(C) = {m : hmin <= T} contains top10(x)
// for every x in C:  m in top10(x) => h_m(x) <= h_10th(x) <= T, hmin <= h_m(x).
__global__ void __launch_bounds__(TPB) cell_kernel() {
    __shared__ int swcnt[8];
    int tid = threadIdx.x;
    int cid = blockIdx.x;
    const float csz = 1.0f / GRIDC;
    float x0a = (float)(cid & (GRIDC - 1)) * csz;
    float x1a = (float)(cid >> 5) * csz;
    float x0b = x0a + csz, x1b = x1a + csz;
    float ccx = x0a + 0.5f * csz, ccy = x1a + 0.5f * csz;
    float hx = 0.5f * csz;

    float hmin[4], hmax[4];
    #pragma unroll
    for (int r = 0; r < 4; ++r) {
        int m = r * TPB + tid;
        float4 c = g_c4[m];
        float k1 = g_k1[m];
        float hm = 0.0f;
        #pragma unroll
        for (int cc = 0; cc < 4; ++cc) {
            float px = (cc & 1) ? x0b : x0a;
            float py = (cc & 2) ? x1b : x1a;
            float u0 = fmaf(c.x, px, fmaf(c.y, py, c.z));
            float u1 = fmaf(c.w, py, k1);
            hm = fmaxf(hm, fmaf(u0, u0, u1 * u1));
        }
        hmax[r] = hm;
        float u0c = fmaf(c.x, ccx, fmaf(c.y, ccy, c.z));
        float u1c = fmaf(c.w, ccy, k1);
        float r0 = (fabsf(c.x) + fabsf(c.y)) * hx;
        float r1 = fabsf(c.w) * hx;
        float lo0 = fmaxf(fabsf(u0c) - r0, 0.0f);
        float lo1 = fmaxf(fabsf(u1c) - r1, 0.0f);
        hmin[r] = fmaf(lo0, lo0, lo1 * lo1);
    }

    auto cta_count = [&](float thr) -> int {
        int c = 0;
        #pragma unroll
        for (int r = 0; r < 4; ++r) c += (hmax[r] <= thr) ? 1 : 0;
        c = __reduce_add_sync(0xFFFFFFFFu, c);
        __syncthreads();                    // protect swcnt reuse
        if ((tid & 31) == 0) swcnt[tid >> 5] = c;
        __syncthreads();
        int tot = 0;
        #pragma unroll
        for (int w = 0; w < 8; ++w) tot += swcnt[w];
        return tot;
    };

    // bisection: maintain count(hmax <= hi) >= 10  =>  hi >= exact 10th hmax
    float lo = 0.0f, hi = 512.0f;
    #pragma unroll 1
    for (int it = 0; it < 6 && cta_count(hi) < KSEL; ++it) hi *= 8.0f;
    #pragma unroll 1
    for (int it = 0; it < 14; ++it) {
        float mid = 0.5f * (lo + hi);
        if (cta_count(mid) >= KSEL) hi = mid; else lo = mid;
    }
    float T = hi * 1.001f + 1e-4f;          // fp-safety margin (inflate)

    // deterministic m-ordered compaction of {m : hmin <= T}
    int base = 0;
    #pragma unroll 1
    for (int r = 0; r < 4; ++r) {
        bool f = (hmin[r] * 0.999f - 1e-4f) <= T;   // fp-safety margin (deflate)
        unsigned b = __ballot_sync(0xFFFFFFFFu, f);
        int lane = tid & 31;
        int myoff = __popc(b & ((1u << lane) - 1u));
        __syncthreads();
        if (lane == 0) swcnt[tid >> 5] = __popc(b);
        __syncthreads();
        int wbase = base;
        for (int w = 0; w < (tid >> 5); ++w) wbase += swcnt[w];
        int rtot = 0;
        #pragma unroll
        for (int w = 0; w < 8; ++w) rtot += swcnt[w];
        if (f) {
            int idx = wbase + myoff;
            if (idx < CAP) g_list[cid * CAP + idx] = (unsigned short)(r * TPB + tid);
        }
        base += rtot;
    }
    if (tid == 0) g_cnt[cid] = base;
}

__device__ __forceinline__ float ex2_approx(float x) {
    float r;
    asm("ex2.approx.ftz.f32 %0, %1;" : "=f"(r) : "f"(x));
    return r;
}

// Depth-2 branchless sorted insert into ASCENDING top[0..9] (keep 10 smallest).
// Stable for equal keys: a later equal value never displaces an earlier one.
__device__ __forceinline__ void siftf(float top[KSEL], float h) {
    float mx[KSEL - 1];
    #pragma unroll
    for (int j = 1; j < KSEL; ++j) mx[j - 1] = fmaxf(h, top[j - 1]);
    #pragma unroll
    for (int j = 1; j < KSEL; ++j) top[j] = fminf(mx[j - 1], top[j]);
    top[0] = fminf(top[0], h);
}

// 2 lanes per point: lane s scans candidate-list entries j == s (mod 2).
__global__ void __launch_bounds__(TPB) render_kernel(
    const float2* __restrict__ x,
    const float*  __restrict__ cols,
    float*        __restrict__ out)
{
    int tid = threadIdx.x;
    int gt  = blockIdx.x * TPB + tid;
    int p   = gt >> 1;
    int s   = gt & 1;
    float2 xv = __ldg(&x[p]);
    int cx = min(GRIDC - 1, (int)(xv.x * (float)GRIDC));
    int cy = min(GRIDC - 1, (int)(xv.y * (float)GRIDC));
    int cid = cy * GRIDC + cx;
    int n   = __ldg(&g_cnt[cid]);
    bool fb = (n > CAP);                         // overflow -> exact full scan
    int nl  = fb ? (M_G >> 1) : ((n - s + 1) >> 1);
    const unsigned short* lst = &g_list[cid * CAP + s];

    auto getm = [&](int j) -> int {
        return fb ? (2 * j + s) : (int)__ldg(&lst[2 * j]);
    };
    // identical fp expression in both passes -> bitwise-reproducible h
    auto evalh = [&](const float4 c, float k1) -> float {
        float u0 = fmaf(c.x, xv.x, fmaf(c.y, xv.y, c.z));
        float u1 = fmaf(c.w, xv.y, k1);
        return fmaf(u0, u0, u1 * u1);
    };

    float top[KSEL];
    #pragma unroll
    for (int j = 0; j < KSEL; ++j) top[j] = POSINF;

    // ---- pass 1: sift all candidates (coeff prefetch one ahead) ----
    {
        int m0 = getm(0);
        float4 c = __ldg(&g_c4[m0]);
        float k1 = __ldg(&g_k1[m0]);
        #pragma unroll 1
        for (int j = 0; j < nl; ++j) {
            float4 cc = c; float kk = k1;
            int mn = getm(j + 1 < nl ? j + 1 : j);
            c  = __ldg(&g_c4[mn]);
            k1 = __ldg(&g_k1[mn]);
            siftf(top, evalh(cc, kk));
        }
    }

    // ---- merge the 2 lane lists -> exact 10 smallest ----
    {
        float cur[KSEL];
        #pragma unroll
        for (int j = 0; j < KSEL; ++j) cur[j] = top[j];
        #pragma unroll
        for (int j = 0; j < KSEL; ++j)
            siftf(top, __shfl_xor_sync(0xFFFFFFFFu, cur[j], 1));
    }
    float t = top[KSEL - 1];                     // exact 10th-smallest h

    // ---- pass 2: accumulate h < t; collect h == t ties (ascending m) ----
    float r0 = 0.f, r1 = 0.f, r2 = 0.f, den = 0.f;
    int ltc = 0, eqc = 0;
    int t0 = 0x7FFFFFFF, t1 = 0x7FFFFFFF, t2 = 0x7FFFFFFF, t3 = 0x7FFFFFFF;

    auto acc = [&](int m, float h) {
        float v = ex2_approx(-h);
        r0 = fmaf(v, __ldg(&cols[3 * m + 0]), r0);
        r1 = fmaf(v, __ldg(&cols[3 * m + 1]), r1);
        r2 = fmaf(v, __ldg(&cols[3 * m + 2]), r2);
        den += v;
    };

    #pragma unroll 1
    for (int j = 0; j < nl; ++j) {
        int m = getm(j);
        float4 c = __ldg(&g_c4[m]);
        float k1 = __ldg(&g_k1[m]);
        float h = evalh(c, k1);
        if (h < t) { acc(m, h); ltc++; }
        else if (h == t) {
            if      (eqc == 0) t0 = m;
            else if (eqc == 1) t1 = m;
            else if (eqc == 2) t2 = m;
            else if (eqc == 3) t3 = m;
            eqc++;
        }
    }
    int myc = min(eqc, 4);

    // ---- exact tie fill: keep lowest-m ties until exactly 10 selected ----
    int lt_o = __shfl_xor_sync(0xFFFFFFFFu, ltc, 1);
    int keep = KSEL - (ltc + lt_o);              // >= 1 by definition of t
    int ptr = 0;
    #pragma unroll
    for (int itr = 0; itr < 4; ++itr) {
        int mym = (ptr == 0) ? t0 : (ptr == 1) ? t1 : (ptr == 2) ? t2 : t3;
        if (ptr >= myc) mym = 0x7FFFFFFF;
        int om = __shfl_xor_sync(0xFFFFFFFFu, mym, 1);
        int w = min(mym, om);
        if (keep > 0 && w != 0x7FFFFFFF) {
            if (mym == w) { acc(w, t); ptr++; }
            keep--;
        }
    }

    // ---- pair reduction + write ----
    r0  += __shfl_xor_sync(0xFFFFFFFFu, r0,  1);
    r1  += __shfl_xor_sync(0xFFFFFFFFu, r1,  1);
    r2  += __shfl_xor_sync(0xFFFFFFFFu, r2,  1);
    den += __shfl_xor_sync(0xFFFFFFFFu, den, 1);

    if (s == 0) {
        float inv = 1.0f / (den + 1e-6f);
        out[3 * p + 0] = r0 * inv;
        out[3 * p + 1] = r1 * inv;
        out[3 * p + 2] = r2 * inv;
    }
}

extern "C" void kernel_launch(void* const* d_in, const int* in_sizes, int n_in,
                              void* d_out, int out_size) {
    const float* xx   = (const float*)d_in[0];   // [N, 2]
    const float* mus  = (const float*)d_in[1];   // [1, M, 2]
    const float* covs = (const float*)d_in[2];   // [1, M, 2, 2]
    const float* cols = (const float*)d_in[3];   // [1, M, 3]
    float* out = (float*)d_out;                  // [N, 3]

    prep_kernel<<<(M_G + 127) / 128, 128>>>(mus, covs);
    cell_kernel<<<NCELL, TPB>>>();
    render_kernel<<<(N_PTS * 2) / TPB, TPB>>>((const float2*)xx, cols, out);
}